// round 3
// baseline (speedup 1.0000x reference)
#include <cuda_runtime.h>

#define B_   64
#define S_   200
#define DK_  32
#define NQ1  4097

// Persistent device state (no allocations allowed in kernel_launch).
static __device__ float g_h[B_ * NQ1 * DK_];       // h state  (33.6 MB)
static __device__ float g_ht[S_ * B_ * DK_];       // h_tilde per step
static __device__ float g_learn[S_ * B_ * DK_];    // all_learning [t][b][k]
static __device__ float g_it[S_ * B_ * DK_];       // it_emb      [t][b][k]

typedef unsigned long long ull;

__device__ __forceinline__ ull ffma2(ull a, ull b, ull c) {
    ull d;
    asm("fma.rn.f32x2 %0, %1, %2, %3;" : "=l"(d) : "l"(a), "l"(b), "l"(c));
    return d;
}
__device__ __forceinline__ ull fadd2(ull a, ull b) {
    ull d;
    asm("add.rn.f32x2 %0, %1, %2;" : "=l"(d) : "l"(a), "l"(b));
    return d;
}
__device__ __forceinline__ void upk2(ull v, float& lo, float& hi) {
    asm("mov.b64 {%0,%1}, %2;" : "=f"(lo), "=f"(hi) : "l"(v));
}

// ---------------------------------------------------------------------------
// K1: init h state (broadcast h0 over batch), zero h_tilde buffers, pred[:,0]=0
// ---------------------------------------------------------------------------
__global__ void k_init(const float* __restrict__ h0, float* __restrict__ pred) {
    int stride = gridDim.x * blockDim.x;
    int gid = blockIdx.x * blockDim.x + threadIdx.x;
    for (int i = gid; i < B_ * NQ1 * DK_; i += stride) {
        int nk = i % (NQ1 * DK_);
        g_h[i] = h0[nk];
    }
    for (int i = gid; i < S_ * B_ * DK_; i += stride) {
        g_ht[i] = 0.0f;
    }
    if (gid < B_) pred[gid * S_] = 0.0f;
}

// ---------------------------------------------------------------------------
// K2: precompute all_learning[t][b][k] and it_emb[t][b][k] for all t
// ---------------------------------------------------------------------------
__global__ void k_embed(const int* __restrict__ e_data, const int* __restrict__ at_data,
                        const int* __restrict__ it_data, const float* __restrict__ a_data,
                        const float* __restrict__ E_e, const float* __restrict__ E_at,
                        const float* __restrict__ E_it,
                        const float* __restrict__ W1, const float* __restrict__ b1) {
    int idx = blockIdx.x * blockDim.x + threadIdx.x;
    if (idx >= S_ * B_ * DK_) return;
    int t = idx / (B_ * DK_);
    int rem = idx - t * (B_ * DK_);
    int b = rem >> 5;
    int k = rem & 31;

    int e  = e_data[b * S_ + t];
    int at = at_data[b * S_ + t];
    int it = it_data[b * S_ + t];
    float a = a_data[b * S_ + t];

    const float* ee  = E_e  + e  * DK_;
    const float* eat = E_at + at * DK_;
    const float* w1k = W1 + k * (3 * DK_);

    float s = b1[k];
    float ws = 0.0f;
#pragma unroll
    for (int j = 0; j < DK_; j++) {
        s = fmaf(ee[j],  w1k[j],        s);
        s = fmaf(eat[j], w1k[DK_ + j],  s);
        ws += w1k[2 * DK_ + j];
    }
    s = fmaf(a, ws, s);

    g_learn[(t * B_ + b) * DK_ + k] = s;
    g_it[(t * B_ + b) * DK_ + k]    = E_it[it * DK_ + k];
}

// ---------------------------------------------------------------------------
// K3: h_tilde0[b] = sum_n q[e_data[b,0], n] * h0[n,:]
// ---------------------------------------------------------------------------
__global__ void k_ht0(const int* __restrict__ e_data, const float* __restrict__ q,
                      const float* __restrict__ h0) {
    int b = blockIdx.x;
    int w = threadIdx.x >> 5;
    int lane = threadIdx.x & 31;
    const float* qr = q + (long)e_data[b * S_] * NQ1;
    float acc = 0.0f;
    for (int n = w; n < NQ1; n += 8) {
        float qv = qr[n];
        if (qv != 0.0f) acc = fmaf(qv, h0[n * DK_ + lane], acc);
    }
    atomicAdd(&g_ht[b * DK_ + lane], acc);
}

// ---------------------------------------------------------------------------
// Kstep(t): one RNN step. grid = (17, 64), 256 threads, 3 blocks/SM.
//   warp0: stages x locally, computes LG[b], c[b].
//   warp1 (bx==0): y_{t-1} -> pred[b][t].
//   all warps: issue W/q loads BEFORE the single barrier; row tile main loop.
// ---------------------------------------------------------------------------
__global__ void __launch_bounds__(256, 3)
k_step(int t, const int* __restrict__ e_data, const float* __restrict__ q,
       const float* __restrict__ E_e,
       const float* __restrict__ W2, const float* __restrict__ b2,
       const float* __restrict__ W3, const float* __restrict__ b3,
       const float* __restrict__ W4, const float* __restrict__ b4,
       const float* __restrict__ W5, const float* __restrict__ b5,
       float* __restrict__ pred) {
    __shared__ float sh_x[4 * DK_];
    __shared__ float sh_LG[DK_];
    __shared__ float sh_c[DK_];

    const int b = blockIdx.y;
    const int tid = threadIdx.x;
    const int w = tid >> 5;
    const int lane = tid & 31;

    const int e_t = e_data[b * S_ + t];
    const int e_n = e_data[b * S_ + t + 1];
    const float* qe_row = q + (long)e_t * NQ1;
    const float* qn_row = q + (long)e_n * NQ1;

    // ---- issue long-latency loads first (overlap with barrier wait) ----
    // Each lane holds W4h[lane, 0..31] as 16 f32x2 registers.
    ull w2r[16];
    {
        const ulonglong2* wp = reinterpret_cast<const ulonglong2*>(W4 + lane * (3 * DK_));
#pragma unroll
        for (int i = 0; i < 8; i++) {
            ulonglong2 p = __ldg(wp + i);
            w2r[2 * i] = p.x;
            w2r[2 * i + 1] = p.y;
        }
    }
    // Coalesced q preload for this warp's 32-row tile (replaces 64 uniform
    // per-row DRAM-latency loads with 2 coalesced ones).
    const int base = (blockIdx.x * 8 + w) * 32;
    const int rl = base + lane;
    float qe_l = 0.0f, qn_l = 0.0f;
    if (rl < NQ1) {
        qe_l = __ldg(qe_row + rl);
        qn_l = __ldg(qn_row + rl);
    }

    if (w == 0) {
        // Stage x = [learning_pre, it, learning, h_tilde_pre] — warp-local.
        float x0 = (t == 0) ? 0.0f : g_learn[((t - 1) * B_ + b) * DK_ + lane];
        float x1 = g_it[(t * B_ + b) * DK_ + lane];
        float x2 = g_learn[(t * B_ + b) * DK_ + lane];
        float x3 = g_ht[(t * B_ + b) * DK_ + lane];
        sh_x[lane]            = x0;
        sh_x[DK_ + lane]      = x1;
        sh_x[2 * DK_ + lane]  = x2;
        sh_x[3 * DK_ + lane]  = x3;
        __syncwarp();

        int k = lane;
        const float* w2k = W2 + k * 128;
        const float* w3k = W3 + k * 128;
        float lg = b2[k];
        float gl = b3[k];
#pragma unroll 16
        for (int j = 0; j < 128; j++) {
            float xv = sh_x[j];
            lg = fmaf(xv, w2k[j], lg);
            gl = fmaf(xv, w3k[j], gl);
        }
        lg = tanhf(lg);
        gl = 1.0f / (1.0f + expf(-gl));
        float LG = gl * (lg + 1.0f) * 0.5f;
        sh_LG[k] = LG;
        __syncwarp();
        const float* w4k = W4 + k * (3 * DK_);
        float c = b4[k];
#pragma unroll
        for (int j = 0; j < DK_; j++) {
            c = fmaf(sh_LG[j], w4k[DK_ + j], c);
            c = fmaf(sh_x[DK_ + j], w4k[2 * DK_ + j], c);
        }
        sh_c[k] = c;
    } else if (w == 1 && blockIdx.x == 0 && t > 0) {
        // y_{t-1}: uses g_ht[t] (completed last step) and E_e[e_data[:, t]]
        int k = lane;
        const float* ee = E_e + e_t * DK_;
        const float* ht = g_ht + (t * B_ + b) * DK_;
        const float* w5k = W5 + k * (2 * DK_);
        float z = b5[k];
#pragma unroll
        for (int j = 0; j < DK_; j++) {
            z = fmaf(ee[j], w5k[j], z);
            z = fmaf(ht[j], w5k[DK_ + j], z);
        }
        float s = 1.0f / (1.0f + expf(-z));
#pragma unroll
        for (int off = 16; off; off >>= 1)
            s += __shfl_xor_sync(0xffffffffu, s, off);
        if (lane == 0) pred[b * S_ + t] = s * (1.0f / DK_);
    }
    __syncthreads();

    const float LGk = sh_LG[lane];
    const float ck = sh_c[lane];
    float* htn = g_ht + ((t + 1) * B_ + b) * DK_;

    const int nrows = min(32, NQ1 - base);

#define ROW_BODY(R)                                                            \
    {                                                                          \
        const int row = base + (R);                                            \
        const int hb = (b * NQ1 + row) * DK_;                                  \
        const ulonglong2* hp = reinterpret_cast<const ulonglong2*>(g_h + hb);  \
        float hk = __ldg(g_h + hb + lane);                                     \
        ull a0 = 0ull, a1 = 0ull, a2 = 0ull, a3 = 0ull;                        \
        _Pragma("unroll")                                                      \
        for (int i = 0; i < 4; i++) {                                          \
            ulonglong2 p0 = __ldg(hp + 2 * i);                                 \
            ulonglong2 p1 = __ldg(hp + 2 * i + 1);                             \
            a0 = ffma2(p0.x, w2r[4 * i + 0], a0);                              \
            a1 = ffma2(p0.y, w2r[4 * i + 1], a1);                              \
            a2 = ffma2(p1.x, w2r[4 * i + 2], a2);                              \
            a3 = ffma2(p1.y, w2r[4 * i + 3], a3);                              \
        }                                                                      \
        float qe = __shfl_sync(0xffffffffu, qe_l, (R));                        \
        float qn = __shfl_sync(0xffffffffu, qn_l, (R));                        \
        ull ssum = fadd2(fadd2(a0, a1), fadd2(a2, a3));                        \
        float lo, hi;                                                          \
        upk2(ssum, lo, hi);                                                    \
        float z = lo + hi + ck;                                                \
        float ex = __expf(-z);                                                 \
        float gm = __fdividef(1.0f, 1.0f + ex);                                \
        float hn = fmaf(gm, hk, qe * LGk);                                     \
        g_h[hb + lane] = hn;                                                   \
        if (qn != 0.0f) atomicAdd(htn + lane, qn * hn);                        \
    }

    if (nrows == 32) {
#pragma unroll 2
        for (int r = 0; r < 32; ++r) ROW_BODY(r)
    } else {
        for (int r = 0; r < nrows; ++r) ROW_BODY(r)
    }
#undef ROW_BODY
}

// ---------------------------------------------------------------------------
// Kfinal: y_{S-2} -> pred[:, S-1]
// ---------------------------------------------------------------------------
__global__ void k_final(const int* __restrict__ e_data, const float* __restrict__ E_e,
                        const float* __restrict__ W5, const float* __restrict__ b5,
                        float* __restrict__ pred) {
    int b = blockIdx.x;
    int k = threadIdx.x;
    int tlast = S_ - 1;
    int en = e_data[b * S_ + tlast];
    const float* ee = E_e + en * DK_;
    const float* ht = g_ht + (tlast * B_ + b) * DK_;
    const float* w5k = W5 + k * (2 * DK_);
    float z = b5[k];
#pragma unroll
    for (int j = 0; j < DK_; j++) {
        z = fmaf(ee[j], w5k[j], z);
        z = fmaf(ht[j], w5k[DK_ + j], z);
    }
    float s = 1.0f / (1.0f + expf(-z));
#pragma unroll
    for (int off = 16; off; off >>= 1)
        s += __shfl_xor_sync(0xffffffffu, s, off);
    if (k == 0) pred[b * S_ + tlast] = s * (1.0f / DK_);
}

// ---------------------------------------------------------------------------
extern "C" void kernel_launch(void* const* d_in, const int* in_sizes, int n_in,
                              void* d_out, int out_size) {
    const int*   e_data  = (const int*)d_in[0];
    const int*   at_data = (const int*)d_in[1];
    const int*   it_data = (const int*)d_in[2];
    const float* a_data  = (const float*)d_in[3];
    const float* q       = (const float*)d_in[4];
    const float* E_e     = (const float*)d_in[5];
    const float* E_at    = (const float*)d_in[6];
    const float* E_it    = (const float*)d_in[7];
    const float* W1      = (const float*)d_in[8];
    const float* b1      = (const float*)d_in[9];
    const float* W2      = (const float*)d_in[10];
    const float* b2      = (const float*)d_in[11];
    const float* W3      = (const float*)d_in[12];
    const float* b3      = (const float*)d_in[13];
    const float* W4      = (const float*)d_in[14];
    const float* b4      = (const float*)d_in[15];
    const float* W5      = (const float*)d_in[16];
    const float* b5      = (const float*)d_in[17];
    const float* h0      = (const float*)d_in[18];
    float* pred = (float*)d_out;

    k_init<<<2048, 256>>>(h0, pred);
    k_embed<<<(S_ * B_ * DK_ + 255) / 256, 256>>>(e_data, at_data, it_data, a_data,
                                                  E_e, E_at, E_it, W1, b1);
    k_ht0<<<B_, 256>>>(e_data, q, h0);

    for (int t = 0; t < S_ - 1; t++) {
        k_step<<<dim3(17, B_), 256>>>(t, e_data, q, E_e,
                                      W2, b2, W3, b3, W4, b4, W5, b5, pred);
    }
    k_final<<<B_, 32>>>(e_data, E_e, W5, b5, pred);
}

// round 4
// speedup vs baseline: 2.0841x; 2.0841x over previous
#include <cuda_runtime.h>

#define B_   64
#define S_   200
#define DK_  32
#define NQ1  4097
#define GX   6
#define CHUNK 64
#define STAGES 4

// Persistent device state (no allocations allowed in kernel_launch).
static __device__ float g_h[B_ * NQ1 * DK_];       // h state  (33.6 MB)
static __device__ float g_ht[S_ * B_ * DK_];       // h_tilde per step
static __device__ float g_learn[S_ * B_ * DK_];    // all_learning [t][b][k]
static __device__ float g_it[S_ * B_ * DK_];       // it_emb      [t][b][k]

typedef unsigned long long ull;

__device__ __forceinline__ ull ffma2(ull a, ull b, ull c) {
    ull d;
    asm("fma.rn.f32x2 %0, %1, %2, %3;" : "=l"(d) : "l"(a), "l"(b), "l"(c));
    return d;
}
__device__ __forceinline__ ull fadd2(ull a, ull b) {
    ull d;
    asm("add.rn.f32x2 %0, %1, %2;" : "=l"(d) : "l"(a), "l"(b));
    return d;
}
__device__ __forceinline__ void upk2(ull v, float& lo, float& hi) {
    asm("mov.b64 {%0,%1}, %2;" : "=f"(lo), "=f"(hi) : "l"(v));
}
__device__ __forceinline__ unsigned smem_u32(const void* p) {
    unsigned a;
    asm("{ .reg .u64 t; cvta.to.shared.u64 t, %1; cvt.u32.u64 %0, t; }" : "=r"(a) : "l"(p));
    return a;
}
__device__ __forceinline__ void cp_async16(unsigned saddr, const void* gaddr) {
    asm volatile("cp.async.cg.shared.global [%0], [%1], 16;" :: "r"(saddr), "l"(gaddr));
}
#define CP_COMMIT() asm volatile("cp.async.commit_group;")
#define CP_WAIT(n)  asm volatile("cp.async.wait_group %0;" :: "n"(n))

// ---------------------------------------------------------------------------
// K1: init h state (broadcast h0 over batch), zero h_tilde buffers, pred[:,0]=0
// ---------------------------------------------------------------------------
__global__ void k_init(const float* __restrict__ h0, float* __restrict__ pred) {
    int stride = gridDim.x * blockDim.x;
    int gid = blockIdx.x * blockDim.x + threadIdx.x;
    for (int i = gid; i < B_ * NQ1 * DK_; i += stride) {
        int nk = i % (NQ1 * DK_);
        g_h[i] = h0[nk];
    }
    for (int i = gid; i < S_ * B_ * DK_; i += stride) {
        g_ht[i] = 0.0f;
    }
    if (gid < B_) pred[gid * S_] = 0.0f;
}

// ---------------------------------------------------------------------------
// K2: precompute all_learning[t][b][k] and it_emb[t][b][k] for all t
// ---------------------------------------------------------------------------
__global__ void k_embed(const int* __restrict__ e_data, const int* __restrict__ at_data,
                        const int* __restrict__ it_data, const float* __restrict__ a_data,
                        const float* __restrict__ E_e, const float* __restrict__ E_at,
                        const float* __restrict__ E_it,
                        const float* __restrict__ W1, const float* __restrict__ b1) {
    int idx = blockIdx.x * blockDim.x + threadIdx.x;
    if (idx >= S_ * B_ * DK_) return;
    int t = idx / (B_ * DK_);
    int rem = idx - t * (B_ * DK_);
    int b = rem >> 5;
    int k = rem & 31;

    int e  = e_data[b * S_ + t];
    int at = at_data[b * S_ + t];
    int it = it_data[b * S_ + t];
    float a = a_data[b * S_ + t];

    const float* ee  = E_e  + e  * DK_;
    const float* eat = E_at + at * DK_;
    const float* w1k = W1 + k * (3 * DK_);

    float s = b1[k];
    float ws = 0.0f;
#pragma unroll
    for (int j = 0; j < DK_; j++) {
        s = fmaf(ee[j],  w1k[j],        s);
        s = fmaf(eat[j], w1k[DK_ + j],  s);
        ws += w1k[2 * DK_ + j];
    }
    s = fmaf(a, ws, s);

    g_learn[(t * B_ + b) * DK_ + k] = s;
    g_it[(t * B_ + b) * DK_ + k]    = E_it[it * DK_ + k];
}

// ---------------------------------------------------------------------------
// K3: h_tilde0[b] = sum_n q[e_data[b,0], n] * h0[n,:]
// ---------------------------------------------------------------------------
__global__ void k_ht0(const int* __restrict__ e_data, const float* __restrict__ q,
                      const float* __restrict__ h0) {
    int b = blockIdx.x;
    int w = threadIdx.x >> 5;
    int lane = threadIdx.x & 31;
    const float* qr = q + (long)e_data[b * S_] * NQ1;
    float acc = 0.0f;
    for (int n = w; n < NQ1; n += 8) {
        float qv = qr[n];
        if (qv != 0.0f) acc = fmaf(qv, h0[n * DK_ + lane], acc);
    }
    atomicAdd(&g_ht[b * DK_ + lane], acc);
}

// ---------------------------------------------------------------------------
// Kstep(t): one RNN step. grid = (GX, 64), 256 threads, 3 blocks/SM.
//   h rows are staged into smem by a 4-deep cp.async pipeline (coalesced),
//   compute reads them via LDS broadcast. warp0 computes LG/c for the block's
//   batch while the pipeline fills; warp1 (bx==0) emits y_{t-1}.
// ---------------------------------------------------------------------------
__global__ void __launch_bounds__(256, 3)
k_step(int t, const int* __restrict__ e_data, const float* __restrict__ q,
       const float* __restrict__ E_e,
       const float* __restrict__ W2, const float* __restrict__ b2,
       const float* __restrict__ W3, const float* __restrict__ b3,
       const float* __restrict__ W4, const float* __restrict__ b4,
       const float* __restrict__ W5, const float* __restrict__ b5,
       float* __restrict__ pred) {
    __shared__ __align__(16) float sh_h[STAGES][CHUNK * DK_];  // 32 KB
    __shared__ float sh_x[4 * DK_];
    __shared__ float sh_LG[DK_];
    __shared__ float sh_c[DK_];

    const int b = blockIdx.y;
    const int tid = threadIdx.x;
    const int w = tid >> 5;
    const int lane = tid & 31;

    const int e_t = e_data[b * S_ + t];
    const int e_n = e_data[b * S_ + t + 1];
    const float* qe_row = q + (long)e_t * NQ1;
    const float* qn_row = q + (long)e_n * NQ1;

    const int rstart = (blockIdx.x * NQ1) / GX;
    const int rend = ((blockIdx.x + 1) * NQ1) / GX;
    const int nchunks = (rend - rstart + CHUNK - 1) / CHUNK;

    // ---- kick off the cp.async pipeline: prefetch STAGES-1 chunks ----
#pragma unroll
    for (int pc = 0; pc < STAGES - 1; pc++) {
        if (pc < nchunks) {
            int rs = rstart + pc * CHUNK;
            int nf16 = (min(rend - rs, CHUNK)) * (DK_ / 4);  // 16B units
            unsigned sdst = smem_u32(&sh_h[pc][0]);
            const float* src = g_h + ((long)b * NQ1 + rs) * DK_;
            for (int i = tid; i < nf16; i += 256)
                cp_async16(sdst + i * 16, src + i * 4);
        }
        CP_COMMIT();
    }

    // Each lane holds W4h[lane, 0..31] as 16 f32x2 registers.
    ull w2r[16];
    {
        const ulonglong2* wp = reinterpret_cast<const ulonglong2*>(W4 + lane * (3 * DK_));
#pragma unroll
        for (int i = 0; i < 8; i++) {
            ulonglong2 p = __ldg(wp + i);
            w2r[2 * i] = p.x;
            w2r[2 * i + 1] = p.y;
        }
    }

    if (w == 0) {
        // Stage x = [learning_pre, it, learning, h_tilde_pre] — warp-local.
        float x0 = (t == 0) ? 0.0f : g_learn[((t - 1) * B_ + b) * DK_ + lane];
        float x1 = g_it[(t * B_ + b) * DK_ + lane];
        float x2 = g_learn[(t * B_ + b) * DK_ + lane];
        float x3 = g_ht[(t * B_ + b) * DK_ + lane];
        sh_x[lane]            = x0;
        sh_x[DK_ + lane]      = x1;
        sh_x[2 * DK_ + lane]  = x2;
        sh_x[3 * DK_ + lane]  = x3;
        __syncwarp();

        int k = lane;
        const float* w2k = W2 + k * 128;
        const float* w3k = W3 + k * 128;
        float lg = b2[k];
        float gl = b3[k];
#pragma unroll 16
        for (int j = 0; j < 128; j++) {
            float xv = sh_x[j];
            lg = fmaf(xv, w2k[j], lg);
            gl = fmaf(xv, w3k[j], gl);
        }
        lg = tanhf(lg);
        gl = 1.0f / (1.0f + expf(-gl));
        float LG = gl * (lg + 1.0f) * 0.5f;
        sh_LG[k] = LG;
        __syncwarp();
        const float* w4k = W4 + k * (3 * DK_);
        float c = b4[k];
#pragma unroll
        for (int j = 0; j < DK_; j++) {
            c = fmaf(sh_LG[j], w4k[DK_ + j], c);
            c = fmaf(sh_x[DK_ + j], w4k[2 * DK_ + j], c);
        }
        sh_c[k] = c;
    } else if (w == 1 && blockIdx.x == 0 && t > 0) {
        // y_{t-1}: uses g_ht[t] (completed last step) and E_e[e_data[:, t]]
        int k = lane;
        const float* ee = E_e + e_t * DK_;
        const float* ht = g_ht + (t * B_ + b) * DK_;
        const float* w5k = W5 + k * (2 * DK_);
        float z = b5[k];
#pragma unroll
        for (int j = 0; j < DK_; j++) {
            z = fmaf(ee[j], w5k[j], z);
            z = fmaf(ht[j], w5k[DK_ + j], z);
        }
        float s = 1.0f / (1.0f + expf(-z));
#pragma unroll
        for (int off = 16; off; off >>= 1)
            s += __shfl_xor_sync(0xffffffffu, s, off);
        if (lane == 0) pred[b * S_ + t] = s * (1.0f / DK_);
    }
    __syncthreads();

    const float LGk = sh_LG[lane];
    const float ck = sh_c[lane];
    float* htn = g_ht + ((t + 1) * B_ + b) * DK_;

    for (int c = 0; c < nchunks; c++) {
        CP_WAIT(STAGES - 2);
        __syncthreads();

        const int slot = c & (STAGES - 1);
        const int rs = rstart + c * CHUNK;
        const int nr = min(rend - rs, CHUNK);

        // per-warp q slice for its 8 rows (lanes 0-7: qe, lanes 8-15: qn)
        const int wr0 = rs + w * 8;
        float qv = 0.0f;
        if (lane < 16) {
            int qr_i = wr0 + (lane & 7);
            if (qr_i < rend && (w * 8 + (lane & 7)) < nr)
                qv = (lane < 8) ? __ldg(qe_row + qr_i) : __ldg(qn_row + qr_i);
        }

        const int wrows = min(max(nr - w * 8, 0), 8);
#pragma unroll
        for (int j = 0; j < 8; j++) {
            if (j >= wrows) break;
            const int row = wr0 + j;
            const float* srow = &sh_h[slot][(w * 8 + j) * DK_];
            const ulonglong2* hp = reinterpret_cast<const ulonglong2*>(srow);
            float hk = srow[lane];
            ull a0 = 0ull, a1 = 0ull, a2 = 0ull, a3 = 0ull;
#pragma unroll
            for (int i = 0; i < 4; i++) {
                ulonglong2 p0 = hp[2 * i];
                ulonglong2 p1 = hp[2 * i + 1];
                a0 = ffma2(p0.x, w2r[4 * i + 0], a0);
                a1 = ffma2(p0.y, w2r[4 * i + 1], a1);
                a2 = ffma2(p1.x, w2r[4 * i + 2], a2);
                a3 = ffma2(p1.y, w2r[4 * i + 3], a3);
            }
            float qe = __shfl_sync(0xffffffffu, qv, j);
            float qn = __shfl_sync(0xffffffffu, qv, 8 + j);
            ull ssum = fadd2(fadd2(a0, a1), fadd2(a2, a3));
            float lo, hi;
            upk2(ssum, lo, hi);
            float z = lo + hi + ck;
            float ex = __expf(-z);
            float gm = __fdividef(1.0f, 1.0f + ex);
            float hn = fmaf(gm, hk, qe * LGk);
            g_h[((long)b * NQ1 + row) * DK_ + lane] = hn;
            if (qn != 0.0f) atomicAdd(htn + lane, qn * hn);
        }
        __syncthreads();

        // prefetch chunk c + STAGES-1 (slot just freed), or empty commit
        const int pc = c + STAGES - 1;
        if (pc < nchunks) {
            int prs = rstart + pc * CHUNK;
            int nf16 = (min(rend - prs, CHUNK)) * (DK_ / 4);
            unsigned sdst = smem_u32(&sh_h[pc & (STAGES - 1)][0]);
            const float* src = g_h + ((long)b * NQ1 + prs) * DK_;
            for (int i = tid; i < nf16; i += 256)
                cp_async16(sdst + i * 16, src + i * 4);
        }
        CP_COMMIT();
    }
}

// ---------------------------------------------------------------------------
// Kfinal: y_{S-2} -> pred[:, S-1]
// ---------------------------------------------------------------------------
__global__ void k_final(const int* __restrict__ e_data, const float* __restrict__ E_e,
                        const float* __restrict__ W5, const float* __restrict__ b5,
                        float* __restrict__ pred) {
    int b = blockIdx.x;
    int k = threadIdx.x;
    int tlast = S_ - 1;
    int en = e_data[b * S_ + tlast];
    const float* ee = E_e + en * DK_;
    const float* ht = g_ht + (tlast * B_ + b) * DK_;
    const float* w5k = W5 + k * (2 * DK_);
    float z = b5[k];
#pragma unroll
    for (int j = 0; j < DK_; j++) {
        z = fmaf(ee[j], w5k[j], z);
        z = fmaf(ht[j], w5k[DK_ + j], z);
    }
    float s = 1.0f / (1.0f + expf(-z));
#pragma unroll
    for (int off = 16; off; off >>= 1)
        s += __shfl_xor_sync(0xffffffffu, s, off);
    if (k == 0) pred[b * S_ + tlast] = s * (1.0f / DK_);
}

// ---------------------------------------------------------------------------
extern "C" void kernel_launch(void* const* d_in, const int* in_sizes, int n_in,
                              void* d_out, int out_size) {
    const int*   e_data  = (const int*)d_in[0];
    const int*   at_data = (const int*)d_in[1];
    const int*   it_data = (const int*)d_in[2];
    const float* a_data  = (const float*)d_in[3];
    const float* q       = (const float*)d_in[4];
    const float* E_e     = (const float*)d_in[5];
    const float* E_at    = (const float*)d_in[6];
    const float* E_it    = (const float*)d_in[7];
    const float* W1      = (const float*)d_in[8];
    const float* b1      = (const float*)d_in[9];
    const float* W2      = (const float*)d_in[10];
    const float* b2      = (const float*)d_in[11];
    const float* W3      = (const float*)d_in[12];
    const float* b3      = (const float*)d_in[13];
    const float* W4      = (const float*)d_in[14];
    const float* b4      = (const float*)d_in[15];
    const float* W5      = (const float*)d_in[16];
    const float* b5      = (const float*)d_in[17];
    const float* h0      = (const float*)d_in[18];
    float* pred = (float*)d_out;

    k_init<<<2048, 256>>>(h0, pred);
    k_embed<<<(S_ * B_ * DK_ + 255) / 256, 256>>>(e_data, at_data, it_data, a_data,
                                                  E_e, E_at, E_it, W1, b1);
    k_ht0<<<B_, 256>>>(e_data, q, h0);

    for (int t = 0; t < S_ - 1; t++) {
        k_step<<<dim3(GX, B_), 256>>>(t, e_data, q, E_e,
                                      W2, b2, W3, b3, W4, b4, W5, b5, pred);
    }
    k_final<<<B_, 32>>>(e_data, E_e, W5, b5, pred);
}

// round 5
// speedup vs baseline: 3.1537x; 1.5132x over previous
#include <cuda_runtime.h>

#define B_      64
#define S_      200
#define DK_     32
#define NQ1     4097
#define GX      6
#define CHUNK   64
#define NCH_TOT 65            // ceil(4097/64)
#define TSTEPS  (S_ - 1)      // 199

// Persistent device state (no allocations allowed in kernel_launch).
static __device__ float g_h[(B_ * NQ1 + CHUNK) * DK_];   // h state + pad row-chunk
static __device__ float g_ht[S_ * B_ * DK_];             // h_tilde per step
static __device__ float g_learn[S_ * B_ * DK_];          // all_learning [t][b][k]
static __device__ float g_it[S_ * B_ * DK_];             // it_emb      [t][b][k]
static __device__ int   g_flag[B_];                      // per-batch step counter

typedef unsigned long long ull;

__device__ __forceinline__ ull ffma2(ull a, ull b, ull c) {
    ull d;
    asm("fma.rn.f32x2 %0, %1, %2, %3;" : "=l"(d) : "l"(a), "l"(b), "l"(c));
    return d;
}
__device__ __forceinline__ ull fadd2(ull a, ull b) {
    ull d;
    asm("add.rn.f32x2 %0, %1, %2;" : "=l"(d) : "l"(a), "l"(b));
    return d;
}
__device__ __forceinline__ void upk2(ull v, float& lo, float& hi) {
    asm("mov.b64 {%0,%1}, %2;" : "=f"(lo), "=f"(hi) : "l"(v));
}
__device__ __forceinline__ unsigned smem_u32(const void* p) {
    unsigned a;
    asm("{ .reg .u64 t; cvta.to.shared.u64 t, %1; cvt.u32.u64 %0, t; }" : "=r"(a) : "l"(p));
    return a;
}
__device__ __forceinline__ void bulk_g2s(unsigned sdst, const void* gsrc, unsigned bytes,
                                         unsigned mbar) {
    asm volatile(
        "cp.async.bulk.shared::cta.global.mbarrier::complete_tx::bytes [%0], [%1], %2, [%3];"
        :: "r"(sdst), "l"(gsrc), "r"(bytes), "r"(mbar) : "memory");
}
__device__ __forceinline__ void mbar_wait(unsigned mbar, unsigned phase) {
    asm volatile(
        "{\n\t.reg .pred P;\n\t"
        "W_%=:\n\t"
        "mbarrier.try_wait.parity.shared.b64 P, [%0], %1, 0x989680;\n\t"
        "@P bra D_%=;\n\t"
        "bra.uni W_%=;\n\t"
        "D_%=:\n\t}"
        :: "r"(mbar), "r"(phase) : "memory");
}

// ---------------------------------------------------------------------------
// K1: init h, zero h_tilde buffers, zero flags, pred[:,0]=0
// ---------------------------------------------------------------------------
__global__ void k_init(const float* __restrict__ h0, float* __restrict__ pred) {
    int stride = gridDim.x * blockDim.x;
    int gid = blockIdx.x * blockDim.x + threadIdx.x;
    for (int i = gid; i < B_ * NQ1 * DK_; i += stride) {
        int nk = i % (NQ1 * DK_);
        g_h[i] = h0[nk];
    }
    for (int i = gid; i < S_ * B_ * DK_; i += stride) g_ht[i] = 0.0f;
    if (gid < B_) { pred[gid * S_] = 0.0f; g_flag[gid] = 0; }
}

// ---------------------------------------------------------------------------
// K2: precompute all_learning[t][b][k] and it_emb[t][b][k]
// ---------------------------------------------------------------------------
__global__ void k_embed(const int* __restrict__ e_data, const int* __restrict__ at_data,
                        const int* __restrict__ it_data, const float* __restrict__ a_data,
                        const float* __restrict__ E_e, const float* __restrict__ E_at,
                        const float* __restrict__ E_it,
                        const float* __restrict__ W1, const float* __restrict__ b1) {
    int idx = blockIdx.x * blockDim.x + threadIdx.x;
    if (idx >= S_ * B_ * DK_) return;
    int t = idx / (B_ * DK_);
    int rem = idx - t * (B_ * DK_);
    int b = rem >> 5;
    int k = rem & 31;

    int e  = e_data[b * S_ + t];
    int at = at_data[b * S_ + t];
    int it = it_data[b * S_ + t];
    float a = a_data[b * S_ + t];

    const float* ee  = E_e  + e  * DK_;
    const float* eat = E_at + at * DK_;
    const float* w1k = W1 + k * (3 * DK_);

    float s = b1[k];
    float ws = 0.0f;
#pragma unroll
    for (int j = 0; j < DK_; j++) {
        s = fmaf(ee[j],  w1k[j],        s);
        s = fmaf(eat[j], w1k[DK_ + j],  s);
        ws += w1k[2 * DK_ + j];
    }
    s = fmaf(a, ws, s);

    g_learn[(t * B_ + b) * DK_ + k] = s;
    g_it[(t * B_ + b) * DK_ + k]    = E_it[it * DK_ + k];
}

// ---------------------------------------------------------------------------
// K3: h_tilde0[b] = sum_n q[e_data[b,0], n] * h0[n,:]
// ---------------------------------------------------------------------------
__global__ void k_ht0(const int* __restrict__ e_data, const float* __restrict__ q,
                      const float* __restrict__ h0) {
    int b = blockIdx.x;
    int w = threadIdx.x >> 5;
    int lane = threadIdx.x & 31;
    const float* qr = q + (long)e_data[b * S_] * NQ1;
    float acc = 0.0f;
    for (int n = w; n < NQ1; n += 8) {
        float qv = qr[n];
        if (qv != 0.0f) acc = fmaf(qv, h0[n * DK_ + lane], acc);
    }
    atomicAdd(&g_ht[b * DK_ + lane], acc);
}

// ---------------------------------------------------------------------------
// k_seq: persistent kernel over all 199 steps. grid = (GX, 64), 256 thr, 3/SM.
//   - h+q chunks staged via cp.async.bulk (1 UBLKCP each) into a 4-slot ring
//   - per-batch flag sync replaces kernel launches
// ---------------------------------------------------------------------------
__global__ void __launch_bounds__(256, 3)
k_seq(const int* __restrict__ e_data, const float* __restrict__ q,
      const float* __restrict__ E_e,
      const float* __restrict__ W2, const float* __restrict__ b2,
      const float* __restrict__ W3, const float* __restrict__ b3,
      const float* __restrict__ W4, const float* __restrict__ b4,
      const float* __restrict__ W5, const float* __restrict__ b5,
      float* __restrict__ pred) {
    __shared__ __align__(16) float sh_h[4][CHUNK * DK_];   // 32 KB
    __shared__ __align__(16) float sh_qe[4][80];
    __shared__ __align__(16) float sh_qn[4][80];
    __shared__ __align__(8)  ull   sh_mbar[4];
    __shared__ float sh_x[4 * DK_];
    __shared__ float sh_LG[DK_];
    __shared__ float sh_c[DK_];

    const int b = blockIdx.y;
    const int bx = blockIdx.x;
    const int tid = threadIdx.x;
    const int w = tid >> 5;
    const int lane = tid & 31;

    const int cs = (bx * NCH_TOT) / GX;
    const int ce = ((bx + 1) * NCH_TOT) / GX;
    const int nch = ce - cs;
    const int rstart = cs * CHUNK;
    const int total_u = TSTEPS * nch;

    const unsigned mb0 = smem_u32(&sh_mbar[0]);

    if (tid == 0) {
#pragma unroll
        for (int s = 0; s < 4; s++)
            asm volatile("mbarrier.init.shared.b64 [%0], 1;" :: "r"(mb0 + s * 8));
        asm volatile("fence.proxy.async.shared::cta;" ::: "memory");
    }
    __syncthreads();

    // prefetch issue (tid0 only): one mbarrier + 3 bulk copies per chunk
#define ISSUE_U(U)                                                                      \
    {                                                                                   \
        int tu = (U) / nch;                                                             \
        int cu = (U) - tu * nch;                                                        \
        int rs = rstart + cu * CHUNK;                                                   \
        int slot = (U) & 3;                                                             \
        unsigned mb = mb0 + slot * 8;                                                   \
        asm volatile("mbarrier.arrive.expect_tx.shared.b64 _, [%0], %1;"                \
                     :: "r"(mb), "r"(8736u) : "memory");                                \
        bulk_g2s(smem_u32(&sh_h[slot][0]), g_h + ((long)b * NQ1 + rs) * DK_, 8192u, mb);\
        int etu = e_data[b * S_ + tu];                                                  \
        int enu = e_data[b * S_ + tu + 1];                                              \
        const void* pe = (const void*)(((ull)(q + (long)etu * NQ1 + rs)) & ~15ULL);     \
        const void* pn = (const void*)(((ull)(q + (long)enu * NQ1 + rs)) & ~15ULL);     \
        bulk_g2s(smem_u32(&sh_qe[slot][0]), pe, 272u, mb);                              \
        bulk_g2s(smem_u32(&sh_qn[slot][0]), pn, 272u, mb);                              \
    }

    if (tid == 0) { ISSUE_U(0) ISSUE_U(1) ISSUE_U(2) }
    int u_next = 3;

    // W4h[lane, 0..31] as 16 f32x2 registers — loaded ONCE for all 199 steps.
    ull w2r[16];
    {
        const ulonglong2* wp = reinterpret_cast<const ulonglong2*>(W4 + lane * (3 * DK_));
#pragma unroll
        for (int i = 0; i < 8; i++) {
            ulonglong2 p = __ldg(wp + i);
            w2r[2 * i] = p.x;
            w2r[2 * i + 1] = p.y;
        }
    }

    for (int t = 0; t < TSTEPS; t++) {
        // ---- gate: wait until all 6 blocks of batch b finished step t-1 ----
        if (t > 0) {
            if (tid == 0) {
                int need = 6 * t;
                int v;
                do {
                    asm volatile("ld.global.acquire.gpu.b32 %0, [%1];"
                                 : "=r"(v) : "l"(&g_flag[b]));
                    if (v >= need) break;
                    __nanosleep(64);
                } while (true);
            }
            __syncthreads();
        }

        const int e_t = e_data[b * S_ + t];
        const int e_n = e_data[b * S_ + t + 1];
        const int qoe = e_t & 3;   // (e*4097 + rs) mod 4 float offset
        const int qon = e_n & 3;

        // ---- prologue ----
        if (w == 0) {
            float x0 = (t == 0) ? 0.0f : g_learn[((t - 1) * B_ + b) * DK_ + lane];
            float x1 = g_it[(t * B_ + b) * DK_ + lane];
            float x2 = g_learn[(t * B_ + b) * DK_ + lane];
            float x3 = g_ht[(t * B_ + b) * DK_ + lane];
            sh_x[lane]           = x0;
            sh_x[DK_ + lane]     = x1;
            sh_x[2 * DK_ + lane] = x2;
            sh_x[3 * DK_ + lane] = x3;
            __syncwarp();

            const float4* w2k = reinterpret_cast<const float4*>(W2 + lane * 128);
            const float4* w3k = reinterpret_cast<const float4*>(W3 + lane * 128);
            const float4* xv4 = reinterpret_cast<const float4*>(sh_x);
            float lgA = b2[lane], lgB = 0.f, lgC = 0.f, lgD = 0.f;
            float glA = b3[lane], glB = 0.f, glC = 0.f, glD = 0.f;
#pragma unroll
            for (int j = 0; j < 32; j++) {
                float4 xv = xv4[j];
                float4 wa = w2k[j];
                float4 wb = w3k[j];
                lgA = fmaf(xv.x, wa.x, lgA); lgB = fmaf(xv.y, wa.y, lgB);
                lgC = fmaf(xv.z, wa.z, lgC); lgD = fmaf(xv.w, wa.w, lgD);
                glA = fmaf(xv.x, wb.x, glA); glB = fmaf(xv.y, wb.y, glB);
                glC = fmaf(xv.z, wb.z, glC); glD = fmaf(xv.w, wb.w, glD);
            }
            float lg = (lgA + lgB) + (lgC + lgD);
            float gl = (glA + glB) + (glC + glD);
            lg = tanhf(lg);
            gl = 1.0f / (1.0f + expf(-gl));
            float LG = gl * (lg + 1.0f) * 0.5f;
            sh_LG[lane] = LG;
            __syncwarp();
            const float* w4k = W4 + lane * (3 * DK_);
            float cA = b4[lane], cB = 0.f;
#pragma unroll
            for (int j = 0; j < DK_; j++) {
                cA = fmaf(sh_LG[j], w4k[DK_ + j], cA);
                cB = fmaf(sh_x[DK_ + j], w4k[2 * DK_ + j], cB);
            }
            sh_c[lane] = cA + cB;
        } else if (w == 1 && bx == 0 && t > 0) {
            // y_{t-1} -> pred[b][t]
            const float* ee = E_e + e_t * DK_;
            const float* ht = g_ht + (t * B_ + b) * DK_;
            const float* w5k = W5 + lane * (2 * DK_);
            float z = b5[lane];
#pragma unroll
            for (int j = 0; j < DK_; j++) {
                z = fmaf(ee[j], w5k[j], z);
                z = fmaf(ht[j], w5k[DK_ + j], z);
            }
            float s = 1.0f / (1.0f + expf(-z));
#pragma unroll
            for (int off = 16; off; off >>= 1)
                s += __shfl_xor_sync(0xffffffffu, s, off);
            if (lane == 0) pred[b * S_ + t] = s * (1.0f / DK_);
        }
        __syncthreads();

        const float LGk = sh_LG[lane];
        const float ck = sh_c[lane];
        float* htn = g_ht + ((t + 1) * B_ + b) * DK_;

        for (int c = 0; c < nch; c++) {
            const int u = t * nch + c;
            const int slot = u & 3;
            mbar_wait(mb0 + slot * 8, (u >> 2) & 1);

            const int rs = rstart + c * CHUNK;
            const int nr = min(NQ1 - rs, CHUNK);
            const int w8 = w * 8;
            const int wrows = min(max(nr - w8, 0), 8);

#define ROW_BODY(J)                                                            \
    {                                                                          \
        const int row = rs + w8 + (J);                                         \
        const float* srow = &sh_h[slot][(w8 + (J)) * DK_];                     \
        const ulonglong2* hp = reinterpret_cast<const ulonglong2*>(srow);      \
        float hk = srow[lane];                                                 \
        ull a0 = 0ull, a1 = 0ull, a2 = 0ull, a3 = 0ull;                        \
        _Pragma("unroll")                                                      \
        for (int i = 0; i < 4; i++) {                                          \
            ulonglong2 p0 = hp[2 * i];                                         \
            ulonglong2 p1 = hp[2 * i + 1];                                     \
            a0 = ffma2(p0.x, w2r[4 * i + 0], a0);                              \
            a1 = ffma2(p0.y, w2r[4 * i + 1], a1);                              \
            a2 = ffma2(p1.x, w2r[4 * i + 2], a2);                              \
            a3 = ffma2(p1.y, w2r[4 * i + 3], a3);                              \
        }                                                                      \
        float qe = sh_qe[slot][qoe + w8 + (J)];                                \
        float qn = sh_qn[slot][qon + w8 + (J)];                                \
        ull ssum = fadd2(fadd2(a0, a1), fadd2(a2, a3));                        \
        float lo, hi;                                                          \
        upk2(ssum, lo, hi);                                                    \
        float z = lo + hi + ck;                                                \
        float ex = __expf(-z);                                                 \
        float gm = __fdividef(1.0f, 1.0f + ex);                                \
        float hn = fmaf(gm, hk, qe * LGk);                                     \
        g_h[((long)b * NQ1 + row) * DK_ + lane] = hn;                          \
        if (qn != 0.0f) atomicAdd(htn + lane, qn * hn);                        \
    }

            if (wrows == 8) {
                ROW_BODY(0) ROW_BODY(1) ROW_BODY(2) ROW_BODY(3)
                ROW_BODY(4) ROW_BODY(5) ROW_BODY(6) ROW_BODY(7)
            } else {
                for (int j = 0; j < wrows; j++) ROW_BODY(j)
            }
#undef ROW_BODY
            __syncthreads();
            if (tid == 0 && u_next < total_u) ISSUE_U(u_next)
            u_next++;
        }

        // ---- arrive: my g_ht[t+1] contributions are globally visible ----
        __threadfence();
        __syncthreads();
        if (tid == 0 && t < TSTEPS - 1) atomicAdd(&g_flag[b], 1);
    }
#undef ISSUE_U
}

// ---------------------------------------------------------------------------
// Kfinal: y_{S-2} -> pred[:, S-1]
// ---------------------------------------------------------------------------
__global__ void k_final(const int* __restrict__ e_data, const float* __restrict__ E_e,
                        const float* __restrict__ W5, const float* __restrict__ b5,
                        float* __restrict__ pred) {
    int b = blockIdx.x;
    int k = threadIdx.x;
    int tlast = S_ - 1;
    int en = e_data[b * S_ + tlast];
    const float* ee = E_e + en * DK_;
    const float* ht = g_ht + (tlast * B_ + b) * DK_;
    const float* w5k = W5 + k * (2 * DK_);
    float z = b5[k];
#pragma unroll
    for (int j = 0; j < DK_; j++) {
        z = fmaf(ee[j], w5k[j], z);
        z = fmaf(ht[j], w5k[DK_ + j], z);
    }
    float s = 1.0f / (1.0f + expf(-z));
#pragma unroll
    for (int off = 16; off; off >>= 1)
        s += __shfl_xor_sync(0xffffffffu, s, off);
    if (k == 0) pred[b * S_ + tlast] = s * (1.0f / DK_);
}

// ---------------------------------------------------------------------------
extern "C" void kernel_launch(void* const* d_in, const int* in_sizes, int n_in,
                              void* d_out, int out_size) {
    const int*   e_data  = (const int*)d_in[0];
    const int*   at_data = (const int*)d_in[1];
    const int*   it_data = (const int*)d_in[2];
    const float* a_data  = (const float*)d_in[3];
    const float* q       = (const float*)d_in[4];
    const float* E_e     = (const float*)d_in[5];
    const float* E_at    = (const float*)d_in[6];
    const float* E_it    = (const float*)d_in[7];
    const float* W1      = (const float*)d_in[8];
    const float* b1      = (const float*)d_in[9];
    const float* W2      = (const float*)d_in[10];
    const float* b2      = (const float*)d_in[11];
    const float* W3      = (const float*)d_in[12];
    const float* b3      = (const float*)d_in[13];
    const float* W4      = (const float*)d_in[14];
    const float* b4      = (const float*)d_in[15];
    const float* W5      = (const float*)d_in[16];
    const float* b5      = (const float*)d_in[17];
    const float* h0      = (const float*)d_in[18];
    float* pred = (float*)d_out;

    k_init<<<2048, 256>>>(h0, pred);
    k_embed<<<(S_ * B_ * DK_ + 255) / 256, 256>>>(e_data, at_data, it_data, a_data,
                                                  E_e, E_at, E_it, W1, b1);
    k_ht0<<<B_, 256>>>(e_data, q, h0);

    k_seq<<<dim3(GX, B_), 256>>>(e_data, q, E_e, W2, b2, W3, b3, W4, b4, W5, b5, pred);

    k_final<<<B_, 32>>>(e_data, E_e, W5, b5, pred);
}